// round 4
// baseline (speedup 1.0000x reference)
#include <cuda_runtime.h>
#include <cstdint>

// ---------------------------------------------------------------------------
// Scratch (no allocation allowed -> __device__ globals)
// ---------------------------------------------------------------------------
#define NMAX 100352
static __device__ float g_agg[(size_t)NMAX * 128];
static __device__ float g_y0 [(size_t)NMAX * 128];
static __device__ float g_y1 [(size_t)NMAX * 128];
static __device__ float g_hid[(size_t)NMAX * 64];
static __device__ float g_num[1024];
static __device__ int   g_cnt[1024];

// ---------------------------------------------------------------------------
// Zeroing
// ---------------------------------------------------------------------------
__global__ void k_zero(float4* __restrict__ p, int n4) {
    int i = blockIdx.x * blockDim.x + threadIdx.x;
    int stride = gridDim.x * blockDim.x;
    float4 z = make_float4(0.f, 0.f, 0.f, 0.f);
    for (; i < n4; i += stride) p[i] = z;
}

__global__ void k_zero_small() {
    int i = threadIdx.x;
    if (i < 1024) { g_num[i] = 0.f; g_cnt[i] = 0; }
}

// ---------------------------------------------------------------------------
// Edge scatter: agg[dst] += ew * x[src]
// d=128: one warp per edge (lane j handles float4 j)
// d=64 : half-warp per edge
// ---------------------------------------------------------------------------
__global__ void k_scatter128(const float* __restrict__ x, const int* __restrict__ ei,
                             const float* __restrict__ ew, float* __restrict__ agg, int E) {
    int t = blockIdx.x * blockDim.x + threadIdx.x;
    int e = t >> 5;
    if (e >= E) return;
    int j = t & 31;
    int s = __ldg(ei + e);
    int d = __ldg(ei + E + e);
    float w = __ldg(ew + e);
    float4 v = __ldg((const float4*)(x + (size_t)s * 128) + j);
    float* dst = agg + (size_t)d * 128 + j * 4;
    atomicAdd(dst + 0, v.x * w);
    atomicAdd(dst + 1, v.y * w);
    atomicAdd(dst + 2, v.z * w);
    atomicAdd(dst + 3, v.w * w);
}

__global__ void k_scatter64(const float* __restrict__ x, const int* __restrict__ ei,
                            const float* __restrict__ ew, float* __restrict__ agg, int E) {
    int t = blockIdx.x * blockDim.x + threadIdx.x;
    int e = t >> 4;
    if (e >= E) return;
    int j = t & 15;
    int s = __ldg(ei + e);
    int d = __ldg(ei + E + e);
    float w = __ldg(ew + e);
    float4 v = __ldg((const float4*)(x + (size_t)s * 64) + j);
    float* dst = agg + (size_t)d * 64 + j * 4;
    atomicAdd(dst + 0, v.x * w);
    atomicAdd(dst + 1, v.y * w);
    atomicAdd(dst + 2, v.z * w);
    atomicAdd(dst + 3, v.w * w);
}

// ---------------------------------------------------------------------------
// Fused dual GEMM:  out[M, BN] = A1 @ W1^T + A2 @ W2^T + bias  (optional ReLU)
// A1: [M, K1], A2: [M, K2], W1: [BN, K1], W2: [BN, K2] (row-major).
// Whole (transposed) W lives in SMEM for the block's lifetime; A streamed in
// double-buffered BK=16 slices. 8-wide output per thread, TM rows per thread.
// BN=128 -> TX=16, TY=16, TM=8 (8x8 tile);  BN=64 -> TX=8, TY=32, TM=4.
// ---------------------------------------------------------------------------
template <int BN, int TM>
__global__ void __launch_bounds__(256, 1)
k_gemm(const float* __restrict__ A1, int K1,
       const float* __restrict__ A2, int K2,
       const float* __restrict__ W1, const float* __restrict__ W2,
       const float* __restrict__ bias, float* __restrict__ out,
       int M, int relu) {
    constexpr int BM = 128, BK = 16, WPAD = 4, APAD = 4;
    constexpr int TX = BN / 8;
    constexpr int TY = 256 / TX;
    static_assert(TY * TM == BM, "tile mismatch");
    const int K = K1 + K2;

    extern __shared__ float sm[];
    float* Wt = sm;                              // [K][BN+WPAD]
    float* As = sm + (size_t)K * (BN + WPAD);    // [2][BK][BM+APAD]
    const int tid = threadIdx.x;

    // Load whole W transposed: Wt[k][n]. Consecutive idx -> consecutive k of
    // one n-row -> coalesced global reads. WPAD=4 keeps rows 16B-aligned and
    // limits store bank conflicts to 4-way (one-time cost).
    for (int idx = tid; idx < K * BN; idx += 256) {
        int n = idx / K;
        int k = idx - n * K;
        float v = (k < K1) ? __ldg(W1 + (size_t)n * K1 + k)
                           : __ldg(W2 + (size_t)n * K2 + (k - K1));
        Wt[k * (BN + WPAD) + n] = v;
    }

    const int m0 = blockIdx.x * BM;
    const int tx = tid % TX;
    const int ty = tid / TX;

    float acc[TM][8];
#pragma unroll
    for (int i = 0; i < TM; i++)
#pragma unroll
        for (int j = 0; j < 8; j++) acc[i][j] = 0.f;

    auto loadA = [&](int kt, int stage) {
        int kb = kt * BK;
        const float* A;
        int KA, koff;
        if (kb < K1) { A = A1; KA = K1; koff = kb; }
        else         { A = A2; KA = K2; koff = kb - K1; }
        float* dst = As + stage * (BK * (BM + APAD));
#pragma unroll
        for (int i = 0; i < 2; i++) {
            int lin = tid + i * 256;       // 512 float4s = 128 rows x 4 vecs
            int m = lin >> 2;
            int kv = (lin & 3) * 4;
            float4 v = make_float4(0.f, 0.f, 0.f, 0.f);
            int mg = m0 + m;
            if (mg < M) v = __ldg((const float4*)(A + (size_t)mg * KA + koff + kv));
            dst[(kv + 0) * (BM + APAD) + m] = v.x;
            dst[(kv + 1) * (BM + APAD) + m] = v.y;
            dst[(kv + 2) * (BM + APAD) + m] = v.z;
            dst[(kv + 3) * (BM + APAD) + m] = v.w;
        }
    };

    loadA(0, 0);
    __syncthreads();

    const int NT = K / BK;
    for (int kt = 0; kt < NT; kt++) {
        if (kt + 1 < NT) loadA(kt + 1, (kt + 1) & 1);
        const float* Ast = As + (kt & 1) * (BK * (BM + APAD));
#pragma unroll
        for (int k = 0; k < BK; k++) {
            float b[8];
            const float* wr = Wt + (kt * BK + k) * (BN + WPAD) + tx * 8;
            *(float4*)&b[0] = *(const float4*)(wr);
            *(float4*)&b[4] = *(const float4*)(wr + 4);
            float a[TM];
            const float* ar = Ast + k * (BM + APAD) + ty * TM;
#pragma unroll
            for (int i = 0; i < TM; i += 4)
                *(float4*)&a[i] = *(const float4*)(ar + i);
#pragma unroll
            for (int i = 0; i < TM; i++)
#pragma unroll
                for (int j = 0; j < 8; j++) acc[i][j] += a[i] * b[j];
        }
        __syncthreads();
    }

    float bv[8];
#pragma unroll
    for (int j = 0; j < 8; j++) bv[j] = __ldg(bias + tx * 8 + j);
#pragma unroll
    for (int i = 0; i < TM; i++) {
        int mg = m0 + ty * TM + i;
        if (mg < M) {
            float r[8];
#pragma unroll
            for (int j = 0; j < 8; j++) {
                float v = acc[i][j] + bv[j];
                r[j] = relu ? fmaxf(v, 0.f) : v;
            }
            float* o = out + (size_t)mg * BN + tx * 8;
            *(float4*)(o)     = *(float4*)&r[0];
            *(float4*)(o + 4) = *(float4*)&r[4];
        }
    }
}

// ---------------------------------------------------------------------------
// Readout tail: per-node scalar = dot(hid[n], Wr2) then scatter into graphs
// (br2 folded into k_div; exact since mean(y + c) = mean(y) + c).
// ---------------------------------------------------------------------------
__global__ void k_finalize(const float* __restrict__ hid, const float* __restrict__ Wr2,
                           const int* __restrict__ batch, int N) {
    __shared__ float w[64];
    if (threadIdx.x < 64) w[threadIdx.x] = __ldg(Wr2 + threadIdx.x);
    __syncthreads();
    int n = blockIdx.x * blockDim.x + threadIdx.x;
    if (n >= N) return;
    const float4* h = (const float4*)(hid + (size_t)n * 64);
    float acc = 0.f;
#pragma unroll
    for (int i = 0; i < 16; i++) {
        float4 v = __ldg(h + i);
        acc += v.x * w[4 * i] + v.y * w[4 * i + 1] + v.z * w[4 * i + 2] + v.w * w[4 * i + 3];
    }
    int g = __ldg(batch + n);
    atomicAdd(&g_num[g], acc);
    atomicAdd(&g_cnt[g], 1);
}

__global__ void k_div(const float* __restrict__ br2, float* __restrict__ out) {
    int g = blockIdx.x * blockDim.x + threadIdx.x;
    if (g < 1024) {
        int c = g_cnt[g];
        out[g] = (c > 0) ? (g_num[g] / (float)c + br2[0]) : 0.f;
    }
}

// ---------------------------------------------------------------------------
// Launch
// ---------------------------------------------------------------------------
extern "C" void kernel_launch(void* const* d_in, const int* in_sizes, int n_in,
                              void* d_out, int out_size) {
    const float* x        = (const float*)d_in[0];
    const int*   ei       = (const int*)  d_in[1];
    const float* ew       = (const float*)d_in[2];
    const int*   batch    = (const int*)  d_in[3];
    const float* W_root0  = (const float*)d_in[4];
    const float* W_rel0   = (const float*)d_in[5];
    const float* b0       = (const float*)d_in[6];
    const float* W_root_r = (const float*)d_in[7];
    const float* W_rel_r  = (const float*)d_in[8];
    const float* b_r      = (const float*)d_in[9];
    const float* Wr1      = (const float*)d_in[10];
    const float* br1      = (const float*)d_in[11];
    const float* Wr2      = (const float*)d_in[12];
    const float* br2      = (const float*)d_in[13];

    const int N = in_sizes[0] / 64;   // nodes
    const int E = in_sizes[2];        // edges (edge_attr count)
    const int L = in_sizes[9] / 128;  // extra GraphConv layers (3)
    (void)n_in; (void)out_size;

    float *agg, *y0, *y1, *hid;
    cudaGetSymbolAddress((void**)&agg, g_agg);
    cudaGetSymbolAddress((void**)&y0,  g_y0);
    cudaGetSymbolAddress((void**)&y1,  g_y1);
    cudaGetSymbolAddress((void**)&hid, g_hid);

    // >48KB dynamic SMEM opt-in (idempotent)
    cudaFuncSetAttribute(k_gemm<128, 8>, cudaFuncAttributeMaxDynamicSharedMemorySize, 160 * 1024);
    cudaFuncSetAttribute(k_gemm<64, 4>,  cudaFuncAttributeMaxDynamicSharedMemorySize, 64 * 1024);

    const int mb = (N + 127) / 128;

    // SMEM sizes: K*(BN+4)*4 (weights) + 2*16*132*4 (A stages, 16896B)
    const size_t smem_l0  = (size_t)128 * 132 * 4 + 16896;  // K=128, BN=128
    const size_t smem_l   = (size_t)256 * 132 * 4 + 16896;  // K=256, BN=128
    const size_t smem_hid = (size_t)128 * 68  * 4 + 16896;  // K=128, BN=64

    // ---- Layer 0 (64-d aggregate, K=64+64) ----
    k_zero<<<2048, 256>>>((float4*)agg, N * 64 / 4);
    k_scatter64<<<(E * 16 + 255) / 256, 256>>>(x, ei, ew, agg, E);
    k_gemm<128, 8><<<mb, 256, smem_l0>>>(agg, 64, x, 64, W_rel0, W_root0, b0, y0, N, 0);

    // ---- Layers 1..L (128-d aggregate, K=128+128) ----
    float* yin = y0;
    float* yout = y1;
    for (int l = 0; l < L; l++) {
        const float* Wrel  = W_rel_r  + (size_t)l * 128 * 128;
        const float* Wroot = W_root_r + (size_t)l * 128 * 128;
        const float* bl    = b_r + (size_t)l * 128;
        k_zero<<<4096, 256>>>((float4*)agg, N * 128 / 4);
        k_scatter128<<<(E * 32 + 255) / 256, 256>>>(yin, ei, ew, agg, E);
        k_gemm<128, 8><<<mb, 256, smem_l>>>(agg, 128, yin, 128, Wrel, Wroot, bl, yout, N, 0);
        float* t = yin; yin = yout; yout = t;
    }

    // ---- Readout ----
    k_gemm<64, 4><<<mb, 256, smem_hid>>>(yin, 128, yin, 0, Wr1, Wr1, br1, hid, N, 1);
    k_zero_small<<<1, 1024>>>();
    k_finalize<<<(N + 255) / 256, 256>>>(hid, Wr2, batch, N);
    k_div<<<4, 256>>>(br2, (float*)d_out);
}

// round 6
// speedup vs baseline: 2.0379x; 2.0379x over previous
#include <cuda_runtime.h>
#include <cstdint>

// ---------------------------------------------------------------------------
// Scratch (no allocation allowed -> __device__ globals)
// ---------------------------------------------------------------------------
#define NMAX 100352
static __device__ float g_agg[(size_t)NMAX * 128];
static __device__ float g_y0 [(size_t)NMAX * 128];
static __device__ float g_y1 [(size_t)NMAX * 128];
static __device__ float g_hid[(size_t)NMAX * 64];
static __device__ float g_num[1024];
static __device__ int   g_cnt[1024];

// ---------------------------------------------------------------------------
// Zeroing
// ---------------------------------------------------------------------------
__global__ void k_zero(float4* __restrict__ p, int n4) {
    int i = blockIdx.x * blockDim.x + threadIdx.x;
    int stride = gridDim.x * blockDim.x;
    float4 z = make_float4(0.f, 0.f, 0.f, 0.f);
    for (; i < n4; i += stride) p[i] = z;
}

__global__ void k_zero_small() {
    int i = threadIdx.x;
    if (i < 1024) { g_num[i] = 0.f; g_cnt[i] = 0; }
}

// ---------------------------------------------------------------------------
// Edge scatter: agg[dst] += ew * x[src], using vector REDG (red.global.v4.f32)
// d=128: one warp per edge (lane j handles float4 j);  d=64: half-warp.
// ---------------------------------------------------------------------------
__device__ __forceinline__ void red_add_v4(float* addr, float a, float b, float c, float d) {
    asm volatile("red.global.add.v4.f32 [%0], {%1, %2, %3, %4};"
                 :: "l"(addr), "f"(a), "f"(b), "f"(c), "f"(d) : "memory");
}

__global__ void k_scatter128(const float* __restrict__ x, const int* __restrict__ ei,
                             const float* __restrict__ ew, float* __restrict__ agg, int E) {
    int t = blockIdx.x * blockDim.x + threadIdx.x;
    int e = t >> 5;
    if (e >= E) return;
    int j = t & 31;
    int s = __ldg(ei + e);
    int d = __ldg(ei + E + e);
    float w = __ldg(ew + e);
    float4 v = __ldg((const float4*)(x + (size_t)s * 128) + j);
    red_add_v4(agg + (size_t)d * 128 + j * 4, v.x * w, v.y * w, v.z * w, v.w * w);
}

__global__ void k_scatter64(const float* __restrict__ x, const int* __restrict__ ei,
                            const float* __restrict__ ew, float* __restrict__ agg, int E) {
    int t = blockIdx.x * blockDim.x + threadIdx.x;
    int e = t >> 4;
    if (e >= E) return;
    int j = t & 15;
    int s = __ldg(ei + e);
    int d = __ldg(ei + E + e);
    float w = __ldg(ew + e);
    float4 v = __ldg((const float4*)(x + (size_t)s * 64) + j);
    red_add_v4(agg + (size_t)d * 64 + j * 4, v.x * w, v.y * w, v.z * w, v.w * w);
}

// ---------------------------------------------------------------------------
// TF32 tensor-core dual GEMM with 3-term hi/lo split (fp32-accurate):
//   out[M, BN] = A1 @ W1^T + A2 @ W2^T + bias   (optional ReLU)
// Each fp32 value x is split x = hi + lo (both tf32); products computed as
// hi*hi + hi*lo + lo*hi -> error ~2^-22 relative.
// Block: 128(M) x BN, 256 threads. BN=128: 8 warps as 4(m) x 2(n), warp tile
// 32x64 (MT=2). BN=64: 8 warps stacked in m, warp tile 16x64 (MT=1).
// SMEM per stage: A[128][BK] and W[BN][BK] as hi/lo u32, row-major, +4 pad
// (bank-conflict-free for the m16n8k8 fragment pattern). Double-buffered.
// ---------------------------------------------------------------------------
__device__ __forceinline__ void f2tf(float x, uint32_t& hi, uint32_t& lo) {
    uint32_t h;
    asm("cvt.rna.tf32.f32 %0, %1;" : "=r"(h) : "f"(x));
    float r = x - __uint_as_float(h);
    uint32_t l;
    asm("cvt.rna.tf32.f32 %0, %1;" : "=r"(l) : "f"(r));
    hi = h; lo = l;
}

__device__ __forceinline__ void mma_tf32(float* c, const uint32_t* a, const uint32_t* b) {
    asm volatile(
        "mma.sync.aligned.m16n8k8.row.col.f32.tf32.tf32.f32 "
        "{%0,%1,%2,%3}, {%4,%5,%6,%7}, {%8,%9}, {%0,%1,%2,%3};"
        : "+f"(c[0]), "+f"(c[1]), "+f"(c[2]), "+f"(c[3])
        : "r"(a[0]), "r"(a[1]), "r"(a[2]), "r"(a[3]), "r"(b[0]), "r"(b[1]));
}

template <int BN, int MT>
__global__ void __launch_bounds__(256, 1)
k_gemm_tc(const float* __restrict__ A1, int K1,
          const float* __restrict__ A2, int K2,
          const float* __restrict__ W1, const float* __restrict__ W2,
          const float* __restrict__ bias, float* __restrict__ out,
          int M, int relu) {
    constexpr int BM = 128, BK = 16, LD = BK + 4;       // LD=20 u32 per row
    constexpr int STAGE = (BM + BN) * 2 * LD;           // u32 per stage
    const int K = K1 + K2;
    const int NT_ = K / BK;

    extern __shared__ uint32_t smu[];
    const int tid  = threadIdx.x;
    const int wid  = tid >> 5;
    const int lane = tid & 31;
    const int gid  = lane >> 2;
    const int tg   = lane & 3;
    const int m0   = blockIdx.x * BM;

    const int wm0 = (BN == 128) ? ((wid & 3) * 32) : (wid * 16);
    const int wn0 = (BN == 128) ? ((wid >> 2) * 64) : 0;

    float acc[MT][8][4];
#pragma unroll
    for (int i = 0; i < MT; i++)
#pragma unroll
        for (int j = 0; j < 8; j++)
#pragma unroll
            for (int c = 0; c < 4; c++) acc[i][j][c] = 0.f;

    constexpr int WV = (BN * 4 + 255) / 256;  // W float4s per thread (2 or 1)
    float4 ra[2], rw[2];

    auto ldgStage = [&](int kt) {
        int kb = kt * BK;
        const float* A; int KA, ko;
        if (kb < K1) { A = A1; KA = K1; ko = kb; } else { A = A2; KA = K2; ko = kb - K1; }
#pragma unroll
        for (int i = 0; i < 2; i++) {
            int lin = tid + i * 256;          // 512 float4 = 128 rows x 4
            int m = lin >> 2, kv = (lin & 3) * 4;
            ra[i] = make_float4(0.f, 0.f, 0.f, 0.f);
            int mg = m0 + m;
            if (mg < M) ra[i] = __ldg((const float4*)(A + (size_t)mg * KA + ko + kv));
        }
        const float* W; int KW, wo;
        if (kb < K1) { W = W1; KW = K1; wo = kb; } else { W = W2; KW = K2; wo = kb - K1; }
#pragma unroll
        for (int i = 0; i < WV; i++) {
            int lin = tid + i * 256;
            if (lin < BN * 4) {
                int n = lin >> 2, kv = (lin & 3) * 4;
                rw[i] = __ldg((const float4*)(W + (size_t)n * KW + wo + kv));
            }
        }
    };

    auto stsStage = [&](int stage) {
        uint32_t* Ah = smu + stage * STAGE;
        uint32_t* Al = Ah + BM * LD;
        uint32_t* Wh = Al + BM * LD;
        uint32_t* Wl = Wh + BN * LD;
#pragma unroll
        for (int i = 0; i < 2; i++) {
            int lin = tid + i * 256;
            int m = lin >> 2, kv = (lin & 3) * 4;
            float v[4] = { ra[i].x, ra[i].y, ra[i].z, ra[i].w };
            uint32_t h[4], l[4];
#pragma unroll
            for (int c = 0; c < 4; c++) f2tf(v[c], h[c], l[c]);
            *(uint4*)&Ah[m * LD + kv] = make_uint4(h[0], h[1], h[2], h[3]);
            *(uint4*)&Al[m * LD + kv] = make_uint4(l[0], l[1], l[2], l[3]);
        }
#pragma unroll
        for (int i = 0; i < WV; i++) {
            int lin = tid + i * 256;
            if (lin < BN * 4) {
                int n = lin >> 2, kv = (lin & 3) * 4;
                float v[4] = { rw[i].x, rw[i].y, rw[i].z, rw[i].w };
                uint32_t h[4], l[4];
#pragma unroll
                for (int c = 0; c < 4; c++) f2tf(v[c], h[c], l[c]);
                *(uint4*)&Wh[n * LD + kv] = make_uint4(h[0], h[1], h[2], h[3]);
                *(uint4*)&Wl[n * LD + kv] = make_uint4(l[0], l[1], l[2], l[3]);
            }
        }
    };

    ldgStage(0);
    stsStage(0);

    for (int kt = 0; kt < NT_; kt++) {
        __syncthreads();
        if (kt + 1 < NT_) ldgStage(kt + 1);

        const uint32_t* Ah = smu + (kt & 1) * STAGE;
        const uint32_t* Al = Ah + BM * LD;
        const uint32_t* Wh = Al + BM * LD;
        const uint32_t* Wl = Wh + BN * LD;

#pragma unroll
        for (int k8 = 0; k8 < 2; k8++) {
            const int k0 = k8 * 8;
            uint32_t afh[MT][4], afl[MT][4];
#pragma unroll
            for (int mt = 0; mt < MT; mt++) {
                int mr = wm0 + mt * 16 + gid;
                afh[mt][0] = Ah[(mr)     * LD + k0 + tg];
                afh[mt][1] = Ah[(mr + 8) * LD + k0 + tg];
                afh[mt][2] = Ah[(mr)     * LD + k0 + tg + 4];
                afh[mt][3] = Ah[(mr + 8) * LD + k0 + tg + 4];
                afl[mt][0] = Al[(mr)     * LD + k0 + tg];
                afl[mt][1] = Al[(mr + 8) * LD + k0 + tg];
                afl[mt][2] = Al[(mr)     * LD + k0 + tg + 4];
                afl[mt][3] = Al[(mr + 8) * LD + k0 + tg + 4];
            }
#pragma unroll
            for (int nt = 0; nt < 8; nt++) {
                int n = wn0 + nt * 8 + gid;
                uint32_t bh[2], bl[2];
                bh[0] = Wh[n * LD + k0 + tg];
                bh[1] = Wh[n * LD + k0 + tg + 4];
                bl[0] = Wl[n * LD + k0 + tg];
                bl[1] = Wl[n * LD + k0 + tg + 4];
#pragma unroll
                for (int mt = 0; mt < MT; mt++) {
                    mma_tf32(acc[mt][nt], afh[mt], bh);
                    mma_tf32(acc[mt][nt], afh[mt], bl);
                    mma_tf32(acc[mt][nt], afl[mt], bh);
                }
            }
        }
        if (kt + 1 < NT_) stsStage((kt + 1) & 1);
    }

    // Epilogue: bias (+ReLU) and store.
#pragma unroll
    for (int mt = 0; mt < MT; mt++) {
        int r0 = m0 + wm0 + mt * 16 + gid;
#pragma unroll
        for (int nt = 0; nt < 8; nt++) {
            int col = wn0 + nt * 8 + 2 * tg;
            float b0v = __ldg(bias + col);
            float b1v = __ldg(bias + col + 1);
            float v0 = acc[mt][nt][0] + b0v;
            float v1 = acc[mt][nt][1] + b1v;
            float v2 = acc[mt][nt][2] + b0v;
            float v3 = acc[mt][nt][3] + b1v;
            if (relu) {
                v0 = fmaxf(v0, 0.f); v1 = fmaxf(v1, 0.f);
                v2 = fmaxf(v2, 0.f); v3 = fmaxf(v3, 0.f);
            }
            if (r0 < M)     *(float2*)(out + (size_t)r0 * BN + col)       = make_float2(v0, v1);
            if (r0 + 8 < M) *(float2*)(out + (size_t)(r0 + 8) * BN + col) = make_float2(v2, v3);
        }
    }
}

// ---------------------------------------------------------------------------
// Readout tail: per-node scalar = dot(hid[n], Wr2) then scatter into graphs
// (br2 folded into k_div; exact since mean(y + c) = mean(y) + c).
// ---------------------------------------------------------------------------
__global__ void k_finalize(const float* __restrict__ hid, const float* __restrict__ Wr2,
                           const int* __restrict__ batch, int N) {
    __shared__ float w[64];
    if (threadIdx.x < 64) w[threadIdx.x] = __ldg(Wr2 + threadIdx.x);
    __syncthreads();
    int n = blockIdx.x * blockDim.x + threadIdx.x;
    if (n >= N) return;
    const float4* h = (const float4*)(hid + (size_t)n * 64);
    float acc = 0.f;
#pragma unroll
    for (int i = 0; i < 16; i++) {
        float4 v = __ldg(h + i);
        acc += v.x * w[4 * i] + v.y * w[4 * i + 1] + v.z * w[4 * i + 2] + v.w * w[4 * i + 3];
    }
    int g = __ldg(batch + n);
    atomicAdd(&g_num[g], acc);
    atomicAdd(&g_cnt[g], 1);
}

__global__ void k_div(const float* __restrict__ br2, float* __restrict__ out) {
    int g = blockIdx.x * blockDim.x + threadIdx.x;
    if (g < 1024) {
        int c = g_cnt[g];
        out[g] = (c > 0) ? (g_num[g] / (float)c + br2[0]) : 0.f;
    }
}

// ---------------------------------------------------------------------------
// Launch
// ---------------------------------------------------------------------------
extern "C" void kernel_launch(void* const* d_in, const int* in_sizes, int n_in,
                              void* d_out, int out_size) {
    const float* x        = (const float*)d_in[0];
    const int*   ei       = (const int*)  d_in[1];
    const float* ew       = (const float*)d_in[2];
    const int*   batch    = (const int*)  d_in[3];
    const float* W_root0  = (const float*)d_in[4];
    const float* W_rel0   = (const float*)d_in[5];
    const float* b0       = (const float*)d_in[6];
    const float* W_root_r = (const float*)d_in[7];
    const float* W_rel_r  = (const float*)d_in[8];
    const float* b_r      = (const float*)d_in[9];
    const float* Wr1      = (const float*)d_in[10];
    const float* br1      = (const float*)d_in[11];
    const float* Wr2      = (const float*)d_in[12];
    const float* br2      = (const float*)d_in[13];

    const int N = in_sizes[0] / 64;   // nodes
    const int E = in_sizes[2];        // edges (edge_attr count)
    const int L = in_sizes[9] / 128;  // extra GraphConv layers (3)
    (void)n_in; (void)out_size;

    float *agg, *y0, *y1, *hid;
    cudaGetSymbolAddress((void**)&agg, g_agg);
    cudaGetSymbolAddress((void**)&y0,  g_y0);
    cudaGetSymbolAddress((void**)&y1,  g_y1);
    cudaGetSymbolAddress((void**)&hid, g_hid);

    // Dynamic SMEM: 2 stages * (BM+BN) rows * 2(hi/lo) * 20 u32 * 4B
    const size_t smem128 = 2 * (size_t)(128 + 128) * 2 * 20 * 4;  // 81920
    const size_t smem64  = 2 * (size_t)(128 + 64)  * 2 * 20 * 4;  // 61440
    cudaFuncSetAttribute(k_gemm_tc<128, 2>, cudaFuncAttributeMaxDynamicSharedMemorySize, (int)smem128);
    cudaFuncSetAttribute(k_gemm_tc<64, 1>,  cudaFuncAttributeMaxDynamicSharedMemorySize, (int)smem64);

    const int mb = (N + 127) / 128;

    // ---- Layer 0 (64-d aggregate, K=64+64) ----
    k_zero<<<2048, 256>>>((float4*)agg, N * 64 / 4);
    k_scatter64<<<(E * 16 + 255) / 256, 256>>>(x, ei, ew, agg, E);
    k_gemm_tc<128, 2><<<mb, 256, smem128>>>(agg, 64, x, 64, W_rel0, W_root0, b0, y0, N, 0);

    // ---- Layers 1..L (128-d aggregate, K=128+128) ----
    float* yin = y0;
    float* yout = y1;
    for (int l = 0; l < L; l++) {
        const float* Wrel  = W_rel_r  + (size_t)l * 128 * 128;
        const float* Wroot = W_root_r + (size_t)l * 128 * 128;
        const float* bl    = b_r + (size_t)l * 128;
        k_zero<<<4096, 256>>>((float4*)agg, N * 128 / 4);
        k_scatter128<<<(E * 32 + 255) / 256, 256>>>(yin, ei, ew, agg, E);
        k_gemm_tc<128, 2><<<mb, 256, smem128>>>(agg, 128, yin, 128, Wrel, Wroot, bl, yout, N, 0);
        float* t = yin; yin = yout; yout = t;
    }

    // ---- Readout ----
    k_gemm_tc<64, 1><<<mb, 256, smem64>>>(yin, 128, yin, 0, Wr1, Wr1, br1, hid, N, 1);
    k_zero_small<<<1, 1024>>>();
    k_finalize<<<(N + 255) / 256, 256>>>(hid, Wr2, batch, N);
    k_div<<<4, 256>>>(br2, (float*)d_out);
}

// round 8
// speedup vs baseline: 3.4251x; 1.6807x over previous
#include <cuda_runtime.h>
#include <cstdint>

// ---------------------------------------------------------------------------
// Scratch (no allocation allowed -> __device__ globals)
// ---------------------------------------------------------------------------
#define NMAX 100352
#define EMAX 1600000
static __device__ float g_agg[(size_t)NMAX * 128];
static __device__ float g_y0 [(size_t)NMAX * 128];
static __device__ float g_y1 [(size_t)NMAX * 128];
static __device__ float g_hid[(size_t)NMAX * 64];
static __device__ float g_num[1024];
static __device__ int   g_cnt[1024];
// CSR scratch
static __device__ int   g_deg [NMAX];
static __device__ int   g_excl[NMAX];
static __device__ int   g_bsum[512];
static __device__ int   g_rowp[NMAX + 1];
static __device__ int   g_off [NMAX];
static __device__ int   g_ssrc[EMAX];
static __device__ float g_sw  [EMAX];

// ---------------------------------------------------------------------------
// CSR build: histogram by dst -> exclusive scan -> stable-ish fill
// ---------------------------------------------------------------------------
__global__ void k_zero_int(int* __restrict__ p, int n) {
    int i = blockIdx.x * blockDim.x + threadIdx.x;
    if (i < n) p[i] = 0;
}

__global__ void k_hist(const int* __restrict__ ei, int E, int* __restrict__ deg) {
    int e = blockIdx.x * blockDim.x + threadIdx.x;
    if (e < E) atomicAdd(&deg[__ldg(ei + E + e)], 1);
}

__global__ void k_scan_block(const int* __restrict__ deg, int* __restrict__ excl,
                             int* __restrict__ bsum, int N) {
    __shared__ int s[256];
    int t = threadIdx.x;
    int i = blockIdx.x * 256 + t;
    int v = (i < N) ? deg[i] : 0;
    s[t] = v;
    __syncthreads();
#pragma unroll
    for (int d = 1; d < 256; d <<= 1) {
        int add = (t >= d) ? s[t - d] : 0;
        __syncthreads();
        s[t] += add;
        __syncthreads();
    }
    if (i < N) excl[i] = s[t] - v;
    if (t == 255) bsum[blockIdx.x] = s[255];
}

__global__ void k_scan_sums(int* __restrict__ bsum, int nb) {
    __shared__ int s[512];
    int t = threadIdx.x;
    int v = (t < nb) ? bsum[t] : 0;
    s[t] = v;
    __syncthreads();
#pragma unroll
    for (int d = 1; d < 512; d <<= 1) {
        int add = (t >= d) ? s[t - d] : 0;
        __syncthreads();
        s[t] += add;
        __syncthreads();
    }
    if (t < nb) bsum[t] = s[t] - v;
}

__global__ void k_scan_add(const int* __restrict__ excl, const int* __restrict__ bsum,
                           int* __restrict__ rowp, int* __restrict__ off, int N, int E) {
    int i = blockIdx.x * blockDim.x + threadIdx.x;
    if (i < N) {
        int r = excl[i] + bsum[i >> 8];
        rowp[i] = r;
        off[i] = r;
    }
    if (i == 0) rowp[N] = E;
}

__global__ void k_fill(const int* __restrict__ ei, const float* __restrict__ ew, int E,
                       int* __restrict__ off, int* __restrict__ ssrc, float* __restrict__ sw) {
    int e = blockIdx.x * blockDim.x + threadIdx.x;
    if (e >= E) return;
    int d = __ldg(ei + E + e);
    int p = atomicAdd(&off[d], 1);
    ssrc[p] = __ldg(ei + e);
    sw[p] = __ldg(ew + e);
}

// ---------------------------------------------------------------------------
// Gather aggregation (no atomics): agg[n] = sum_{e in CSR row n} w[e]*x[src[e]]
// d=128: one warp per node, lane = float4 j. 4 nodes per 128-thread block.
// d=64 : 16 lanes per node (float4), 8 nodes per 128-thread block.
// ---------------------------------------------------------------------------
__global__ void k_agg128(const float* __restrict__ x, const int* __restrict__ rowp,
                         const int* __restrict__ ssrc, const float* __restrict__ sw,
                         float* __restrict__ agg, int N) {
    int n = blockIdx.x * 4 + (threadIdx.x >> 5);
    if (n >= N) return;
    int lane = threadIdx.x & 31;
    int e = __ldg(rowp + n), end = __ldg(rowp + n + 1);
    float4 a0 = make_float4(0.f, 0.f, 0.f, 0.f);
    float4 a1 = make_float4(0.f, 0.f, 0.f, 0.f);
    for (; e + 1 < end; e += 2) {
        int s0 = __ldg(ssrc + e),     s1 = __ldg(ssrc + e + 1);
        float w0 = __ldg(sw + e),     w1 = __ldg(sw + e + 1);
        float4 v0 = __ldg((const float4*)(x + (size_t)s0 * 128) + lane);
        float4 v1 = __ldg((const float4*)(x + (size_t)s1 * 128) + lane);
        a0.x += w0 * v0.x; a0.y += w0 * v0.y; a0.z += w0 * v0.z; a0.w += w0 * v0.w;
        a1.x += w1 * v1.x; a1.y += w1 * v1.y; a1.z += w1 * v1.z; a1.w += w1 * v1.w;
    }
    if (e < end) {
        int s0 = __ldg(ssrc + e);
        float w0 = __ldg(sw + e);
        float4 v0 = __ldg((const float4*)(x + (size_t)s0 * 128) + lane);
        a0.x += w0 * v0.x; a0.y += w0 * v0.y; a0.z += w0 * v0.z; a0.w += w0 * v0.w;
    }
    a0.x += a1.x; a0.y += a1.y; a0.z += a1.z; a0.w += a1.w;
    *((float4*)(agg + (size_t)n * 128) + lane) = a0;
}

__global__ void k_agg64(const float* __restrict__ x, const int* __restrict__ rowp,
                        const int* __restrict__ ssrc, const float* __restrict__ sw,
                        float* __restrict__ agg, int N) {
    int n = blockIdx.x * 8 + (threadIdx.x >> 4);
    if (n >= N) return;
    int lane = threadIdx.x & 15;
    int e = __ldg(rowp + n), end = __ldg(rowp + n + 1);
    float4 a0 = make_float4(0.f, 0.f, 0.f, 0.f);
    float4 a1 = make_float4(0.f, 0.f, 0.f, 0.f);
    for (; e + 1 < end; e += 2) {
        int s0 = __ldg(ssrc + e),     s1 = __ldg(ssrc + e + 1);
        float w0 = __ldg(sw + e),     w1 = __ldg(sw + e + 1);
        float4 v0 = __ldg((const float4*)(x + (size_t)s0 * 64) + lane);
        float4 v1 = __ldg((const float4*)(x + (size_t)s1 * 64) + lane);
        a0.x += w0 * v0.x; a0.y += w0 * v0.y; a0.z += w0 * v0.z; a0.w += w0 * v0.w;
        a1.x += w1 * v1.x; a1.y += w1 * v1.y; a1.z += w1 * v1.z; a1.w += w1 * v1.w;
    }
    if (e < end) {
        int s0 = __ldg(ssrc + e);
        float w0 = __ldg(sw + e);
        float4 v0 = __ldg((const float4*)(x + (size_t)s0 * 64) + lane);
        a0.x += w0 * v0.x; a0.y += w0 * v0.y; a0.z += w0 * v0.z; a0.w += w0 * v0.w;
    }
    a0.x += a1.x; a0.y += a1.y; a0.z += a1.z; a0.w += a1.w;
    *((float4*)(agg + (size_t)n * 64) + lane) = a0;
}

// ---------------------------------------------------------------------------
// TF32 tensor-core dual GEMM with 3-term hi/lo split (fp32-accurate):
//   out[M, BN] = A1 @ W1^T + A2 @ W2^T + bias   (optional ReLU)
// ---------------------------------------------------------------------------
__device__ __forceinline__ void f2tf(float x, uint32_t& hi, uint32_t& lo) {
    uint32_t h;
    asm("cvt.rna.tf32.f32 %0, %1;" : "=r"(h) : "f"(x));
    float r = x - __uint_as_float(h);
    uint32_t l;
    asm("cvt.rna.tf32.f32 %0, %1;" : "=r"(l) : "f"(r));
    hi = h; lo = l;
}

__device__ __forceinline__ void mma_tf32(float* c, const uint32_t* a, const uint32_t* b) {
    asm volatile(
        "mma.sync.aligned.m16n8k8.row.col.f32.tf32.tf32.f32 "
        "{%0,%1,%2,%3}, {%4,%5,%6,%7}, {%8,%9}, {%0,%1,%2,%3};"
        : "+f"(c[0]), "+f"(c[1]), "+f"(c[2]), "+f"(c[3])
        : "r"(a[0]), "r"(a[1]), "r"(a[2]), "r"(a[3]), "r"(b[0]), "r"(b[1]));
}

template <int BN, int MT>
__global__ void __launch_bounds__(256, 1)
k_gemm_tc(const float* __restrict__ A1, int K1,
          const float* __restrict__ A2, int K2,
          const float* __restrict__ W1, const float* __restrict__ W2,
          const float* __restrict__ bias, float* __restrict__ out,
          int M, int relu) {
    constexpr int BM = 128, BK = 16, LD = BK + 4;       // LD=20 u32 per row
    constexpr int STAGE = (BM + BN) * 2 * LD;           // u32 per stage
    const int K = K1 + K2;
    const int NT_ = K / BK;

    extern __shared__ uint32_t smu[];
    const int tid  = threadIdx.x;
    const int wid  = tid >> 5;
    const int lane = tid & 31;
    const int gid  = lane >> 2;
    const int tg   = lane & 3;
    const int m0   = blockIdx.x * BM;

    const int wm0 = (BN == 128) ? ((wid & 3) * 32) : (wid * 16);
    const int wn0 = (BN == 128) ? ((wid >> 2) * 64) : 0;

    float acc[MT][8][4];
#pragma unroll
    for (int i = 0; i < MT; i++)
#pragma unroll
        for (int j = 0; j < 8; j++)
#pragma unroll
            for (int c = 0; c < 4; c++) acc[i][j][c] = 0.f;

    constexpr int WV = (BN * 4 + 255) / 256;  // W float4s per thread (2 or 1)
    float4 ra[2], rw[2];

    auto ldgStage = [&](int kt) {
        int kb = kt * BK;
        const float* A; int KA, ko;
        if (kb < K1) { A = A1; KA = K1; ko = kb; } else { A = A2; KA = K2; ko = kb - K1; }
#pragma unroll
        for (int i = 0; i < 2; i++) {
            int lin = tid + i * 256;          // 512 float4 = 128 rows x 4
            int m = lin >> 2, kv = (lin & 3) * 4;
            ra[i] = make_float4(0.f, 0.f, 0.f, 0.f);
            int mg = m0 + m;
            if (mg < M) ra[i] = __ldg((const float4*)(A + (size_t)mg * KA + ko + kv));
        }
        const float* W; int KW, wo;
        if (kb < K1) { W = W1; KW = K1; wo = kb; } else { W = W2; KW = K2; wo = kb - K1; }
#pragma unroll
        for (int i = 0; i < WV; i++) {
            int lin = tid + i * 256;
            if (lin < BN * 4) {
                int n = lin >> 2, kv = (lin & 3) * 4;
                rw[i] = __ldg((const float4*)(W + (size_t)n * KW + wo + kv));
            }
        }
    };

    auto stsStage = [&](int stage) {
        uint32_t* Ah = smu + stage * STAGE;
        uint32_t* Al = Ah + BM * LD;
        uint32_t* Wh = Al + BM * LD;
        uint32_t* Wl = Wh + BN * LD;
#pragma unroll
        for (int i = 0; i < 2; i++) {
            int lin = tid + i * 256;
            int m = lin >> 2, kv = (lin & 3) * 4;
            float v[4] = { ra[i].x, ra[i].y, ra[i].z, ra[i].w };
            uint32_t h[4], l[4];
#pragma unroll
            for (int c = 0; c < 4; c++) f2tf(v[c], h[c], l[c]);
            *(uint4*)&Ah[m * LD + kv] = make_uint4(h[0], h[1], h[2], h[3]);
            *(uint4*)&Al[m * LD + kv] = make_uint4(l[0], l[1], l[2], l[3]);
        }
#pragma unroll
        for (int i = 0; i < WV; i++) {
            int lin = tid + i * 256;
            if (lin < BN * 4) {
                int n = lin >> 2, kv = (lin & 3) * 4;
                float v[4] = { rw[i].x, rw[i].y, rw[i].z, rw[i].w };
                uint32_t h[4], l[4];
#pragma unroll
                for (int c = 0; c < 4; c++) f2tf(v[c], h[c], l[c]);
                *(uint4*)&Wh[n * LD + kv] = make_uint4(h[0], h[1], h[2], h[3]);
                *(uint4*)&Wl[n * LD + kv] = make_uint4(l[0], l[1], l[2], l[3]);
            }
        }
    };

    ldgStage(0);
    stsStage(0);

    for (int kt = 0; kt < NT_; kt++) {
        __syncthreads();
        if (kt + 1 < NT_) ldgStage(kt + 1);

        const uint32_t* Ah = smu + (kt & 1) * STAGE;
        const uint32_t* Al = Ah + BM * LD;
        const uint32_t* Wh = Al + BM * LD;
        const uint32_t* Wl = Wh + BN * LD;

#pragma unroll
        for (int k8 = 0; k8 < 2; k8++) {
            const int k0 = k8 * 8;
            uint32_t afh[MT][4], afl[MT][4];
#pragma unroll
            for (int mt = 0; mt < MT; mt++) {
                int mr = wm0 + mt * 16 + gid;
                afh[mt][0] = Ah[(mr)     * LD + k0 + tg];
                afh[mt][1] = Ah[(mr + 8) * LD + k0 + tg];
                afh[mt][2] = Ah[(mr)     * LD + k0 + tg + 4];
                afh[mt][3] = Ah[(mr + 8) * LD + k0 + tg + 4];
                afl[mt][0] = Al[(mr)     * LD + k0 + tg];
                afl[mt][1] = Al[(mr + 8) * LD + k0 + tg];
                afl[mt][2] = Al[(mr)     * LD + k0 + tg + 4];
                afl[mt][3] = Al[(mr + 8) * LD + k0 + tg + 4];
            }
#pragma unroll
            for (int nt = 0; nt < 8; nt++) {
                int n = wn0 + nt * 8 + gid;
                uint32_t bh[2], bl[2];
                bh[0] = Wh[n * LD + k0 + tg];
                bh[1] = Wh[n * LD + k0 + tg + 4];
                bl[0] = Wl[n * LD + k0 + tg];
                bl[1] = Wl[n * LD + k0 + tg + 4];
#pragma unroll
                for (int mt = 0; mt < MT; mt++) {
                    mma_tf32(acc[mt][nt], afh[mt], bh);
                    mma_tf32(acc[mt][nt], afh[mt], bl);
                    mma_tf32(acc[mt][nt], afl[mt], bh);
                }
            }
        }
        if (kt + 1 < NT_) stsStage((kt + 1) & 1);
    }

    // Epilogue: bias (+ReLU) and store.
#pragma unroll
    for (int mt = 0; mt < MT; mt++) {
        int r0 = m0 + wm0 + mt * 16 + gid;
#pragma unroll
        for (int nt = 0; nt < 8; nt++) {
            int col = wn0 + nt * 8 + 2 * tg;
            float b0v = __ldg(bias + col);
            float b1v = __ldg(bias + col + 1);
            float v0 = acc[mt][nt][0] + b0v;
            float v1 = acc[mt][nt][1] + b1v;
            float v2 = acc[mt][nt][2] + b0v;
            float v3 = acc[mt][nt][3] + b1v;
            if (relu) {
                v0 = fmaxf(v0, 0.f); v1 = fmaxf(v1, 0.f);
                v2 = fmaxf(v2, 0.f); v3 = fmaxf(v3, 0.f);
            }
            if (r0 < M)     *(float2*)(out + (size_t)r0 * BN + col)       = make_float2(v0, v1);
            if (r0 + 8 < M) *(float2*)(out + (size_t)(r0 + 8) * BN + col) = make_float2(v2, v3);
        }
    }
}

// ---------------------------------------------------------------------------
// Readout tail
// ---------------------------------------------------------------------------
__global__ void k_zero_small() {
    int i = threadIdx.x;
    if (i < 1024) { g_num[i] = 0.f; g_cnt[i] = 0; }
}

__global__ void k_finalize(const float* __restrict__ hid, const float* __restrict__ Wr2,
                           const int* __restrict__ batch, int N) {
    __shared__ float w[64];
    if (threadIdx.x < 64) w[threadIdx.x] = __ldg(Wr2 + threadIdx.x);
    __syncthreads();
    int n = blockIdx.x * blockDim.x + threadIdx.x;
    if (n >= N) return;
    const float4* h = (const float4*)(hid + (size_t)n * 64);
    float acc = 0.f;
#pragma unroll
    for (int i = 0; i < 16; i++) {
        float4 v = __ldg(h + i);
        acc += v.x * w[4 * i] + v.y * w[4 * i + 1] + v.z * w[4 * i + 2] + v.w * w[4 * i + 3];
    }
    int g = __ldg(batch + n);
    atomicAdd(&g_num[g], acc);
    atomicAdd(&g_cnt[g], 1);
}

__global__ void k_div(const float* __restrict__ br2, float* __restrict__ out) {
    int g = blockIdx.x * blockDim.x + threadIdx.x;
    if (g < 1024) {
        int c = g_cnt[g];
        out[g] = (c > 0) ? (g_num[g] / (float)c + br2[0]) : 0.f;
    }
}

// ---------------------------------------------------------------------------
// Launch
// ---------------------------------------------------------------------------
extern "C" void kernel_launch(void* const* d_in, const int* in_sizes, int n_in,
                              void* d_out, int out_size) {
    const float* x        = (const float*)d_in[0];
    const int*   ei       = (const int*)  d_in[1];
    const float* ew       = (const float*)d_in[2];
    const int*   batch    = (const int*)  d_in[3];
    const float* W_root0  = (const float*)d_in[4];
    const float* W_rel0   = (const float*)d_in[5];
    const float* b0       = (const float*)d_in[6];
    const float* W_root_r = (const float*)d_in[7];
    const float* W_rel_r  = (const float*)d_in[8];
    const float* b_r      = (const float*)d_in[9];
    const float* Wr1      = (const float*)d_in[10];
    const float* br1      = (const float*)d_in[11];
    const float* Wr2      = (const float*)d_in[12];
    const float* br2      = (const float*)d_in[13];

    const int N = in_sizes[0] / 64;   // nodes
    const int E = in_sizes[2];        // edges
    const int L = in_sizes[9] / 128;  // extra GraphConv layers (3)
    (void)n_in; (void)out_size;

    float *agg, *y0, *y1, *hid, *sw;
    int *deg, *excl, *bsum, *rowp, *off, *ssrc;
    cudaGetSymbolAddress((void**)&agg,  g_agg);
    cudaGetSymbolAddress((void**)&y0,   g_y0);
    cudaGetSymbolAddress((void**)&y1,   g_y1);
    cudaGetSymbolAddress((void**)&hid,  g_hid);
    cudaGetSymbolAddress((void**)&deg,  g_deg);
    cudaGetSymbolAddress((void**)&excl, g_excl);
    cudaGetSymbolAddress((void**)&bsum, g_bsum);
    cudaGetSymbolAddress((void**)&rowp, g_rowp);
    cudaGetSymbolAddress((void**)&off,  g_off);
    cudaGetSymbolAddress((void**)&ssrc, g_ssrc);
    cudaGetSymbolAddress((void**)&sw,   g_sw);

    const size_t smem128 = 2 * (size_t)(128 + 128) * 2 * 20 * 4;  // 81920
    const size_t smem64  = 2 * (size_t)(128 + 64)  * 2 * 20 * 4;  // 61440
    cudaFuncSetAttribute(k_gemm_tc<128, 2>, cudaFuncAttributeMaxDynamicSharedMemorySize, (int)smem128);
    cudaFuncSetAttribute(k_gemm_tc<64, 1>,  cudaFuncAttributeMaxDynamicSharedMemorySize, (int)smem64);

    const int mb = (N + 127) / 128;
    const int nb256 = (N + 255) / 256;
    const int eb = (E + 255) / 256;

    // ---- CSR build (by dst) ----
    k_zero_int<<<nb256, 256>>>(deg, N);
    k_hist<<<eb, 256>>>(ei, E, deg);
    k_scan_block<<<nb256, 256>>>(deg, excl, bsum, N);
    k_scan_sums<<<1, 512>>>(bsum, nb256);
    k_scan_add<<<nb256, 256>>>(excl, bsum, rowp, off, N, E);
    k_fill<<<eb, 256>>>(ei, ew, E, off, ssrc, sw);

    // ---- Layer 0 (64-d aggregate, K=64+64) ----
    k_agg64<<<(N + 7) / 8, 128>>>(x, rowp, ssrc, sw, agg, N);
    k_gemm_tc<128, 2><<<mb, 256, smem128>>>(agg, 64, x, 64, W_rel0, W_root0, b0, y0, N, 0);

    // ---- Layers 1..L (128-d aggregate, K=128+128) ----
    float* yin = y0;
    float* yout = y1;
    for (int l = 0; l < L; l++) {
        const float* Wrel  = W_rel_r  + (size_t)l * 128 * 128;
        const float* Wroot = W_root_r + (size_t)l * 128 * 128;
        const float* bl    = b_r + (size_t)l * 128;
        k_agg128<<<(N + 3) / 4, 128>>>(yin, rowp, ssrc, sw, agg, N);
        k_gemm_tc<128, 2><<<mb, 256, smem128>>>(agg, 128, yin, 128, Wrel, Wroot, bl, yout, N, 0);
        float* t = yin; yin = yout; yout = t;
    }

    // ---- Readout ----
    k_gemm_tc<64, 1><<<mb, 256, smem64>>>(yin, 128, yin, 0, Wr1, Wr1, br1, hid, N, 1);
    k_zero_small<<<1, 1024>>>();
    k_finalize<<<(N + 255) / 256, 256>>>(hid, Wr2, batch, N);
    k_div<<<4, 256>>>(br2, (float*)d_out);
}

// round 12
// speedup vs baseline: 4.3216x; 1.2618x over previous
#include <cuda_runtime.h>
#include <cuda_fp16.h>
#include <cstdint>

// ---------------------------------------------------------------------------
// Scratch (no allocation allowed -> __device__ globals)
// ---------------------------------------------------------------------------
#define NMAX 100352
#define EMAX 1600000
static __device__ float g_agg[(size_t)NMAX * 128];
static __device__ float g_y0 [(size_t)NMAX * 128];
static __device__ float g_y1 [(size_t)NMAX * 128];
static __device__ float g_num[1024];
static __device__ int   g_cnt[1024];
// CSR scratch
static __device__ int   g_deg [NMAX];
static __device__ int   g_excl[NMAX];
static __device__ int   g_bsum[512];
static __device__ int   g_rowp[NMAX + 1];
static __device__ int   g_off [NMAX];
static __device__ int   g_ssrc[EMAX];
static __device__ float g_sw  [EMAX];

// ---------------------------------------------------------------------------
// CSR build: histogram by dst -> exclusive scan -> fill
// ---------------------------------------------------------------------------
__global__ void k_zero_int(int* __restrict__ p, int n) {
    int i = blockIdx.x * blockDim.x + threadIdx.x;
    if (i < n) p[i] = 0;
}

__global__ void k_hist(const int* __restrict__ ei, int E, int* __restrict__ deg) {
    int e = blockIdx.x * blockDim.x + threadIdx.x;
    if (e < E) atomicAdd(&deg[__ldg(ei + E + e)], 1);
}

__global__ void k_scan_block(const int* __restrict__ deg, int* __restrict__ excl,
                             int* __restrict__ bsum, int N) {
    __shared__ int s[256];
    int t = threadIdx.x;
    int i = blockIdx.x * 256 + t;
    int v = (i < N) ? deg[i] : 0;
    s[t] = v;
    __syncthreads();
#pragma unroll
    for (int d = 1; d < 256; d <<= 1) {
        int add = (t >= d) ? s[t - d] : 0;
        __syncthreads();
        s[t] += add;
        __syncthreads();
    }
    if (i < N) excl[i] = s[t] - v;
    if (t == 255) bsum[blockIdx.x] = s[255];
}

__global__ void k_scan_sums(int* __restrict__ bsum, int nb) {
    __shared__ int s[512];
    int t = threadIdx.x;
    int v = (t < nb) ? bsum[t] : 0;
    s[t] = v;
    __syncthreads();
#pragma unroll
    for (int d = 1; d < 512; d <<= 1) {
        int add = (t >= d) ? s[t - d] : 0;
        __syncthreads();
        s[t] += add;
        __syncthreads();
    }
    if (t < nb) bsum[t] = s[t] - v;
}

__global__ void k_scan_add(const int* __restrict__ excl, const int* __restrict__ bsum,
                           int* __restrict__ rowp, int* __restrict__ off, int N, int E) {
    int i = blockIdx.x * blockDim.x + threadIdx.x;
    if (i < N) {
        int r = excl[i] + bsum[i >> 8];
        rowp[i] = r;
        off[i] = r;
    }
    if (i == 0) rowp[N] = E;
}

__global__ void k_fill(const int* __restrict__ ei, const float* __restrict__ ew, int E,
                       int* __restrict__ off, int* __restrict__ ssrc, float* __restrict__ sw) {
    int e = blockIdx.x * blockDim.x + threadIdx.x;
    if (e >= E) return;
    int d = __ldg(ei + E + e);
    int p = atomicAdd(&off[d], 1);
    ssrc[p] = __ldg(ei + e);
    sw[p] = __ldg(ew + e);
}

// ---------------------------------------------------------------------------
// Gather aggregation (no atomics): agg[n] = sum_{e in CSR row n} w[e]*x[src[e]]
// ---------------------------------------------------------------------------
__global__ void k_agg128(const float* __restrict__ x, const int* __restrict__ rowp,
                         const int* __restrict__ ssrc, const float* __restrict__ sw,
                         float* __restrict__ agg, int N) {
    int n = blockIdx.x * 4 + (threadIdx.x >> 5);
    if (n >= N) return;
    int lane = threadIdx.x & 31;
    int e = __ldg(rowp + n), end = __ldg(rowp + n + 1);
    float4 a0 = make_float4(0.f, 0.f, 0.f, 0.f);
    float4 a1 = make_float4(0.f, 0.f, 0.f, 0.f);
    for (; e + 1 < end; e += 2) {
        int s0 = __ldg(ssrc + e),     s1 = __ldg(ssrc + e + 1);
        float w0 = __ldg(sw + e),     w1 = __ldg(sw + e + 1);
        float4 v0 = __ldg((const float4*)(x + (size_t)s0 * 128) + lane);
        float4 v1 = __ldg((const float4*)(x + (size_t)s1 * 128) + lane);
        a0.x += w0 * v0.x; a0.y += w0 * v0.y; a0.z += w0 * v0.z; a0.w += w0 * v0.w;
        a1.x += w1 * v1.x; a1.y += w1 * v1.y; a1.z += w1 * v1.z; a1.w += w1 * v1.w;
    }
    if (e < end) {
        int s0 = __ldg(ssrc + e);
        float w0 = __ldg(sw + e);
        float4 v0 = __ldg((const float4*)(x + (size_t)s0 * 128) + lane);
        a0.x += w0 * v0.x; a0.y += w0 * v0.y; a0.z += w0 * v0.z; a0.w += w0 * v0.w;
    }
    a0.x += a1.x; a0.y += a1.y; a0.z += a1.z; a0.w += a1.w;
    *((float4*)(agg + (size_t)n * 128) + lane) = a0;
}

__global__ void k_agg64(const float* __restrict__ x, const int* __restrict__ rowp,
                        const int* __restrict__ ssrc, const float* __restrict__ sw,
                        float* __restrict__ agg, int N) {
    int n = blockIdx.x * 8 + (threadIdx.x >> 4);
    if (n >= N) return;
    int lane = threadIdx.x & 15;
    int e = __ldg(rowp + n), end = __ldg(rowp + n + 1);
    float4 a0 = make_float4(0.f, 0.f, 0.f, 0.f);
    float4 a1 = make_float4(0.f, 0.f, 0.f, 0.f);
    for (; e + 1 < end; e += 2) {
        int s0 = __ldg(ssrc + e),     s1 = __ldg(ssrc + e + 1);
        float w0 = __ldg(sw + e),     w1 = __ldg(sw + e + 1);
        float4 v0 = __ldg((const float4*)(x + (size_t)s0 * 64) + lane);
        float4 v1 = __ldg((const float4*)(x + (size_t)s1 * 64) + lane);
        a0.x += w0 * v0.x; a0.y += w0 * v0.y; a0.z += w0 * v0.z; a0.w += w0 * v0.w;
        a1.x += w1 * v1.x; a1.y += w1 * v1.y; a1.z += w1 * v1.z; a1.w += w1 * v1.w;
    }
    if (e < end) {
        int s0 = __ldg(ssrc + e);
        float w0 = __ldg(sw + e);
        float4 v0 = __ldg((const float4*)(x + (size_t)s0 * 64) + lane);
        a0.x += w0 * v0.x; a0.y += w0 * v0.y; a0.z += w0 * v0.z; a0.w += w0 * v0.w;
    }
    a0.x += a1.x; a0.y += a1.y; a0.z += a1.z; a0.w += a1.w;
    *((float4*)(agg + (size_t)n * 64) + lane) = a0;
}

// ---------------------------------------------------------------------------
// FP16 tensor-core dual GEMM with 3-term hi/lo split (fp32-accurate):
//   out[M, BN] = A1 @ W1^T + A2 @ W2^T + bias   (optional ReLU)
// v = hi + lo, both fp16 (hi = rn(v); lo = rn(v - hi), exact residual by
// Sterbenz). Products hh + hl + lh -> error ~2^-22 relative.
// m16n8k16 HMMA, fp32 accumulate. BK=16 = one MMA K-step per tile.
// SMEM rows hold 16 fp16 = 8 u32, LDU=12 (+4 pad -> conflict-free fragment
// LDS for the (g,tg) pattern). Double-buffered.
// FIN=true (readout): instead of storing, compute dot(relu(row), Wr2),
// quad-shfl-reduce, atomicAdd into per-graph accumulators.
// ---------------------------------------------------------------------------
__device__ __forceinline__ uint32_t pack_hi(float a, float b, float& ra, float& rb) {
    __half ha = __float2half_rn(a), hb = __float2half_rn(b);
    ra = a - __half2float(ha);
    rb = b - __half2float(hb);
    __half2 p = __halves2half2(ha, hb);
    return *(uint32_t*)&p;
}
__device__ __forceinline__ uint32_t pack_lo(float a, float b) {
    __half2 p = __halves2half2(__float2half_rn(a), __float2half_rn(b));
    return *(uint32_t*)&p;
}

__device__ __forceinline__ void mma_f16(float* c, const uint32_t* a, const uint32_t* b) {
    asm volatile(
        "mma.sync.aligned.m16n8k16.row.col.f32.f16.f16.f32 "
        "{%0,%1,%2,%3}, {%4,%5,%6,%7}, {%8,%9}, {%0,%1,%2,%3};"
        : "+f"(c[0]), "+f"(c[1]), "+f"(c[2]), "+f"(c[3])
        : "r"(a[0]), "r"(a[1]), "r"(a[2]), "r"(a[3]), "r"(b[0]), "r"(b[1]));
}

template <int BN, int MT, bool FIN>
__global__ void __launch_bounds__(256, 1)
k_gemm_tc(const float* __restrict__ A1, int K1,
          const float* __restrict__ A2, int K2,
          const float* __restrict__ W1, const float* __restrict__ W2,
          const float* __restrict__ bias, float* __restrict__ out,
          int M, int relu,
          const float* __restrict__ Wr2v, const int* __restrict__ batchv) {
    constexpr int BM = 128, BK = 16, LDU = 12;          // 8 data u32 + 4 pad
    constexpr int STAGE = (BM + BN) * 2 * LDU;          // u32 per stage
    const int K = K1 + K2;
    const int NT_ = K / BK;

    extern __shared__ uint32_t smu[];
    const int tid  = threadIdx.x;
    const int wid  = tid >> 5;
    const int lane = tid & 31;
    const int gid  = lane >> 2;
    const int tg   = lane & 3;
    const int m0   = blockIdx.x * BM;

    const int wm0 = (BN == 128) ? ((wid & 3) * 32) : (wid * 16);
    const int wn0 = (BN == 128) ? ((wid >> 2) * 64) : 0;

    float acc[MT][8][4];
#pragma unroll
    for (int i = 0; i < MT; i++)
#pragma unroll
        for (int j = 0; j < 8; j++)
#pragma unroll
            for (int c = 0; c < 4; c++) acc[i][j][c] = 0.f;

    constexpr int WV = (BN * 4 + 255) / 256;  // W float4s per thread (2 or 1)
    float4 ra[2], rw[2];

    auto ldgStage = [&](int kt) {
        int kb = kt * BK;
        const float* A; int KA, ko;
        if (kb < K1) { A = A1; KA = K1; ko = kb; } else { A = A2; KA = K2; ko = kb - K1; }
#pragma unroll
        for (int i = 0; i < 2; i++) {
            int lin = tid + i * 256;          // 512 float4 = 128 rows x 4
            int m = lin >> 2, kv = (lin & 3) * 4;
            ra[i] = make_float4(0.f, 0.f, 0.f, 0.f);
            int mg = m0 + m;
            if (mg < M) ra[i] = __ldg((const float4*)(A + (size_t)mg * KA + ko + kv));
        }
        const float* W; int KW, wo;
        if (kb < K1) { W = W1; KW = K1; wo = kb; } else { W = W2; KW = K2; wo = kb - K1; }
#pragma unroll
        for (int i = 0; i < WV; i++) {
            int lin = tid + i * 256;
            if (lin < BN * 4) {
                int n = lin >> 2, kv = (lin & 3) * 4;
                rw[i] = __ldg((const float4*)(W + (size_t)n * KW + wo + kv));
            }
        }
    };

    auto stsStage = [&](int stage) {
        uint32_t* Ah = smu + stage * STAGE;
        uint32_t* Al = Ah + BM * LDU;
        uint32_t* Wh = Al + BM * LDU;
        uint32_t* Wl = Wh + BN * LDU;
#pragma unroll
        for (int i = 0; i < 2; i++) {
            int lin = tid + i * 256;
            int m = lin >> 2, kp = (lin & 3) * 2;   // u32-pair index
            float r0, r1, r2, r3;
            uint32_t h0 = pack_hi(ra[i].x, ra[i].y, r0, r1);
            uint32_t h1 = pack_hi(ra[i].z, ra[i].w, r2, r3);
            *(uint2*)&Ah[m * LDU + kp] = make_uint2(h0, h1);
            *(uint2*)&Al[m * LDU + kp] = make_uint2(pack_lo(r0, r1), pack_lo(r2, r3));
        }
#pragma unroll
        for (int i = 0; i < WV; i++) {
            int lin = tid + i * 256;
            if (lin < BN * 4) {
                int n = lin >> 2, kp = (lin & 3) * 2;
                float r0, r1, r2, r3;
                uint32_t h0 = pack_hi(rw[i].x, rw[i].y, r0, r1);
                uint32_t h1 = pack_hi(rw[i].z, rw[i].w, r2, r3);
                *(uint2*)&Wh[n * LDU + kp] = make_uint2(h0, h1);
                *(uint2*)&Wl[n * LDU + kp] = make_uint2(pack_lo(r0, r1), pack_lo(r2, r3));
            }
        }
    };

    ldgStage(0);
    stsStage(0);

    for (int kt = 0; kt < NT_; kt++) {
        __syncthreads();
        if (kt + 1 < NT_) ldgStage(kt + 1);

        const uint32_t* Ah = smu + (kt & 1) * STAGE;
        const uint32_t* Al = Ah + BM * LDU;
        const uint32_t* Wh = Al + BM * LDU;
        const uint32_t* Wl = Wh + BN * LDU;

        uint32_t afh[MT][4], afl[MT][4];
#pragma unroll
        for (int mt = 0; mt < MT; mt++) {
            int mr = wm0 + mt * 16 + gid;
            afh[mt][0] = Ah[(mr)     * LDU + tg];
            afh[mt][1] = Ah[(mr + 8) * LDU + tg];
            afh[mt][2] = Ah[(mr)     * LDU + tg + 4];
            afh[mt][3] = Ah[(mr + 8) * LDU + tg + 4];
            afl[mt][0] = Al[(mr)     * LDU + tg];
            afl[mt][1] = Al[(mr + 8) * LDU + tg];
            afl[mt][2] = Al[(mr)     * LDU + tg + 4];
            afl[mt][3] = Al[(mr + 8) * LDU + tg + 4];
        }
#pragma unroll
        for (int nt = 0; nt < 8; nt++) {
            int n = wn0 + nt * 8 + gid;
            uint32_t bh[2], bl[2];
            bh[0] = Wh[n * LDU + tg];
            bh[1] = Wh[n * LDU + tg + 4];
            bl[0] = Wl[n * LDU + tg];
            bl[1] = Wl[n * LDU + tg + 4];
#pragma unroll
            for (int mt = 0; mt < MT; mt++) {
                mma_f16(acc[mt][nt], afh[mt], bh);
                mma_f16(acc[mt][nt], afh[mt], bl);
                mma_f16(acc[mt][nt], afl[mt], bh);
            }
        }
        if (kt + 1 < NT_) stsStage((kt + 1) & 1);
    }

    if constexpr (FIN) {
        // Fused MLP-readout tail: per-row dot(relu(row + bias), Wr2),
        // quad reduce, scatter into per-graph sums. MT==1, BN==64.
        float part0 = 0.f, part1 = 0.f;
#pragma unroll
        for (int nt = 0; nt < 8; nt++) {
            int col = nt * 8 + 2 * tg;
            float b0v = __ldg(bias + col);
            float b1v = __ldg(bias + col + 1);
            float w0v = __ldg(Wr2v + col);
            float w1v = __ldg(Wr2v + col + 1);
            part0 += fmaxf(acc[0][nt][0] + b0v, 0.f) * w0v
                   + fmaxf(acc[0][nt][1] + b1v, 0.f) * w1v;
            part1 += fmaxf(acc[0][nt][2] + b0v, 0.f) * w0v
                   + fmaxf(acc[0][nt][3] + b1v, 0.f) * w1v;
        }
        part0 += __shfl_xor_sync(0xffffffffu, part0, 1);
        part0 += __shfl_xor_sync(0xffffffffu, part0, 2);
        part1 += __shfl_xor_sync(0xffffffffu, part1, 1);
        part1 += __shfl_xor_sync(0xffffffffu, part1, 2);
        if (tg == 0) {
            int r0 = m0 + wm0 + gid;
            int r1 = r0 + 8;
            if (r0 < M) {
                int g = __ldg(batchv + r0);
                atomicAdd(&g_num[g], part0);
                atomicAdd(&g_cnt[g], 1);
            }
            if (r1 < M) {
                int g = __ldg(batchv + r1);
                atomicAdd(&g_num[g], part1);
                atomicAdd(&g_cnt[g], 1);
            }
        }
    } else {
#pragma unroll
        for (int mt = 0; mt < MT; mt++) {
            int r0 = m0 + wm0 + mt * 16 + gid;
#pragma unroll
            for (int nt = 0; nt < 8; nt++) {
                int col = wn0 + nt * 8 + 2 * tg;
                float b0v = __ldg(bias + col);
                float b1v = __ldg(bias + col + 1);
                float v0 = acc[mt][nt][0] + b0v;
                float v1 = acc[mt][nt][1] + b1v;
                float v2 = acc[mt][nt][2] + b0v;
                float v3 = acc[mt][nt][3] + b1v;
                if (relu) {
                    v0 = fmaxf(v0, 0.f); v1 = fmaxf(v1, 0.f);
                    v2 = fmaxf(v2, 0.f); v3 = fmaxf(v3, 0.f);
                }
                if (r0 < M)     *(float2*)(out + (size_t)r0 * BN + col)       = make_float2(v0, v1);
                if (r0 + 8 < M) *(float2*)(out + (size_t)(r0 + 8) * BN + col) = make_float2(v2, v3);
            }
        }
    }
}

// ---------------------------------------------------------------------------
// Tail
// ---------------------------------------------------------------------------
__global__ void k_zero_small() {
    int i = threadIdx.x;
    if (i < 1024) { g_num[i] = 0.f; g_cnt[i] = 0; }
}

__global__ void k_div(const float* __restrict__ br2, float* __restrict__ out) {
    int g = blockIdx.x * blockDim.x + threadIdx.x;
    if (g < 1024) {
        int c = g_cnt[g];
        out[g] = (c > 0) ? (g_num[g] / (float)c + br2[0]) : 0.f;
    }
}

// ---------------------------------------------------------------------------
// Launch
// ---------------------------------------------------------------------------
extern "C" void kernel_launch(void* const* d_in, const int* in_sizes, int n_in,
                              void* d_out, int out_size) {
    const float* x        = (const float*)d_in[0];
    const int*   ei       = (const int*)  d_in[1];
    const float* ew       = (const float*)d_in[2];
    const int*   batch    = (const int*)  d_in[3];
    const float* W_root0  = (const float*)d_in[4];
    const float* W_rel0   = (const float*)d_in[5];
    const float* b0       = (const float*)d_in[6];
    const float* W_root_r = (const float*)d_in[7];
    const float* W_rel_r  = (const float*)d_in[8];
    const float* b_r      = (const float*)d_in[9];
    const float* Wr1      = (const float*)d_in[10];
    const float* br1      = (const float*)d_in[11];
    const float* Wr2      = (const float*)d_in[12];
    const float* br2      = (const float*)d_in[13];

    const int N = in_sizes[0] / 64;   // nodes
    const int E = in_sizes[2];        // edges
    const int L = in_sizes[9] / 128;  // extra GraphConv layers (3)
    (void)n_in; (void)out_size;

    float *agg, *y0, *y1, *sw;
    int *deg, *excl, *bsum, *rowp, *off, *ssrc;
    cudaGetSymbolAddress((void**)&agg,  g_agg);
    cudaGetSymbolAddress((void**)&y0,   g_y0);
    cudaGetSymbolAddress((void**)&y1,   g_y1);
    cudaGetSymbolAddress((void**)&deg,  g_deg);
    cudaGetSymbolAddress((void**)&excl, g_excl);
    cudaGetSymbolAddress((void**)&bsum, g_bsum);
    cudaGetSymbolAddress((void**)&rowp, g_rowp);
    cudaGetSymbolAddress((void**)&off,  g_off);
    cudaGetSymbolAddress((void**)&ssrc, g_ssrc);
    cudaGetSymbolAddress((void**)&sw,   g_sw);

    // Dynamic SMEM: 2 stages * (BM+BN) rows * 2(hi/lo) * 12 u32 * 4B
    const size_t smem128 = 2 * (size_t)(128 + 128) * 2 * 12 * 4;  // 49152
    const size_t smem64  = 2 * (size_t)(128 + 64)  * 2 * 12 * 4;  // 36864
    cudaFuncSetAttribute(k_gemm_tc<128, 2, false>, cudaFuncAttributeMaxDynamicSharedMemorySize, (int)smem128);
    cudaFuncSetAttribute(k_gemm_tc<64, 1, true>,   cudaFuncAttributeMaxDynamicSharedMemorySize, (int)smem64);

    const int mb = (N + 127) / 128;
    const int nb256 = (N + 255) / 256;
    const int eb = (E + 255) / 256;

    // ---- CSR build (by dst) ----
    k_zero_int<<<nb256, 256>>>(deg, N);
    k_hist<<<eb, 256>>>(ei, E, deg);
    k_scan_block<<<nb256, 256>>>(deg, excl, bsum, N);
    k_scan_sums<<<1, 512>>>(bsum, nb256);
    k_scan_add<<<nb256, 256>>>(excl, bsum, rowp, off, N, E);
    k_fill<<<eb, 256>>>(ei, ew, E, off, ssrc, sw);

    // ---- Layer 0 (64-d aggregate, K=64+64) ----
    k_agg64<<<(N + 7) / 8, 128>>>(x, rowp, ssrc, sw, agg, N);
    k_gemm_tc<128, 2, false><<<mb, 256, smem128>>>(agg, 64, x, 64, W_rel0, W_root0, b0, y0, N, 0, nullptr, nullptr);

    // ---- Layers 1..L (128-d aggregate, K=128+128) ----
    float* yin = y0;
    float* yout = y1;
    for (int l = 0; l < L; l++) {
        const float* Wrel  = W_rel_r  + (size_t)l * 128 * 128;
        const float* Wroot = W_root_r + (size_t)l * 128 * 128;
        const float* bl    = b_r + (size_t)l * 128;
        k_agg128<<<(N + 3) / 4, 128>>>(yin, rowp, ssrc, sw, agg, N);
        k_gemm_tc<128, 2, false><<<mb, 256, smem128>>>(agg, 128, yin, 128, Wrel, Wroot, bl, yout, N, 0, nullptr, nullptr);
        float* t = yin; yin = yout; yout = t;
    }

    // ---- Readout (fused: GEMM + ReLU + dot(Wr2) + scatter-mean numerators) ----
    k_zero_small<<<1, 1024>>>();
    k_gemm_tc<64, 1, true><<<mb, 256, smem64>>>(yin, 128, yin, 0, Wr1, Wr1, br1, nullptr, N, 1, Wr2, batch);
    k_div<<<4, 256>>>(br2, (float*)d_out);
}